// round 12
// baseline (speedup 1.0000x reference)
#include <cuda_runtime.h>
#include <stdint.h>

#define NN 100000
#define NE 3200000
#define F  16
#define PAD 128            // fixed bucket size; P(deg > 128) ~ 17-sigma ~ 0
#define NBLK ((NN + 255) / 256)

// Scratch (allocation-free rule: __device__ globals)
__device__ __align__(16) int   d_deg[NN];
__device__ __align__(16) int   d_csr[NN * PAD];   // padded buckets, 512B-aligned rows
__device__ __align__(16) float d_dis[NN];
__device__ __align__(16) float d_g[NN * F];       // layer-1 messages
__device__ __align__(16) float d_g2[NN * F];      // layer-2 messages (double buffer)

__global__ void k_zero() {
    int i = blockIdx.x * blockDim.x + threadIdx.x;
    if (i < NN) d_deg[i] = 0;
}

// Single-pass CSR build, 8 edges/thread: off = atomicAdd(deg[dst]); csr[dst*128+off] = src
__global__ void k_build(const int* __restrict__ ei) {
    int t = blockIdx.x * blockDim.x + threadIdx.x;
    if (t >= NE / 8) return;
    const int4* S = (const int4*)ei;
    const int4* D = (const int4*)(ei + NE);
    int4 sa = S[t * 2], sb = S[t * 2 + 1];
    int4 da = D[t * 2], db = D[t * 2 + 1];
    int oa0 = atomicAdd(&d_deg[da.x], 1);
    int oa1 = atomicAdd(&d_deg[da.y], 1);
    int oa2 = atomicAdd(&d_deg[da.z], 1);
    int oa3 = atomicAdd(&d_deg[da.w], 1);
    int ob0 = atomicAdd(&d_deg[db.x], 1);
    int ob1 = atomicAdd(&d_deg[db.y], 1);
    int ob2 = atomicAdd(&d_deg[db.z], 1);
    int ob3 = atomicAdd(&d_deg[db.w], 1);
    d_csr[(da.x << 7) + oa0] = sa.x;
    d_csr[(da.y << 7) + oa1] = sa.y;
    d_csr[(da.z << 7) + oa2] = sa.z;
    d_csr[(da.w << 7) + oa3] = sa.w;
    d_csr[(db.x << 7) + ob0] = sb.x;
    d_csr[(db.y << 7) + ob1] = sb.y;
    d_csr[(db.z << 7) + ob2] = sb.z;
    d_csr[(db.w << 7) + ob3] = sb.w;
}

// Layer-1 init: dis = rsqrt(deg+1); g = dis * (x@W1)
__global__ void k_l1_init(const float* __restrict__ x, const float* __restrict__ W1) {
    __shared__ float sW[F * F];
    int t = threadIdx.x;
    if (t < F * F) sW[t] = W1[t];
    __syncthreads();
    int i = blockIdx.x * blockDim.x + t;
    if (i >= NN) return;

    float dis = rsqrtf((float)(d_deg[i] + 1));
    d_dis[i] = dis;

    float xi[F];
    const float4* xr = (const float4*)(x + (size_t)i * F);
#pragma unroll
    for (int q = 0; q < 4; q++) {
        float4 v = xr[q];
        xi[q * 4 + 0] = v.x; xi[q * 4 + 1] = v.y;
        xi[q * 4 + 2] = v.z; xi[q * 4 + 3] = v.w;
    }
    float4* gp = (float4*)(d_g + (size_t)i * F);
#pragma unroll
    for (int q = 0; q < 4; q++) {
        float4 h;
        float* hp = &h.x;
#pragma unroll
        for (int jj = 0; jj < 4; jj++) {
            int j = q * 4 + jj;
            float a = 0.f;
#pragma unroll
            for (int k = 0; k < F; k++) a = fmaf(xi[k], sW[k * F + j], a);
            hp[jj] = a * dis;
        }
        gp[q] = h;
    }
}

// Shared gather body: thread = (node w, chunk q); lanes 4k..4k+3 share node's edge list
// so each edge's 64B row is fetched fully coalesced. Reads SRC, returns raw acc chunk.
__device__ __forceinline__ float4 gather_chunk(const float* __restrict__ src, int w, int q) {
    const float4* __restrict__ G = (const float4*)src;
    float4 a = G[w * 4 + q];            // self-loop
    int deg = d_deg[w];
    const int4* __restrict__ idx4 = (const int4*)(d_csr + (w << 7));
    int full = deg >> 2;
    for (int k = 0; k < full; k++) {
        int4 s = idx4[k];
        float4 v0 = G[s.x * 4 + q];
        float4 v1 = G[s.y * 4 + q];
        float4 v2 = G[s.z * 4 + q];
        float4 v3 = G[s.w * 4 + q];
        a.x += (v0.x + v1.x) + (v2.x + v3.x);
        a.y += (v0.y + v1.y) + (v2.y + v3.y);
        a.z += (v0.z + v1.z) + (v2.z + v3.z);
        a.w += (v0.w + v1.w) + (v2.w + v3.w);
    }
    const int* __restrict__ rp = d_csr + (w << 7) + (full << 2);
    int rem = deg & 3;
    for (int r = 0; r < rem; r++) {
        float4 v = G[rp[r] * 4 + q];
        a.x += v.x; a.y += v.y; a.z += v.z; a.w += v.w;
    }
    return a;
}

// Gather pass 1 (reads d_g) fused with layer-1 finalize + layer-2 GEMM (writes d_g2):
// h1 = relu(dis*acc + b1) -> smem exchange -> h2 = dis*(h1@W2) -> d_g2
__global__ void k_gather1(const float* __restrict__ b1, const float* __restrict__ W2) {
    __shared__ float sW[F * F];
    __shared__ float sb[F];
    __shared__ float sH[64][F + 1];     // padded: conflict-free row reads
    int t = threadIdx.x;
    if (t < F * F) sW[t] = W2[t];
    if (t < F) sb[t] = b1[t];
    __syncthreads();

    int tid = blockIdx.x * blockDim.x + t;
    int w = tid >> 2;
    int q = tid & 3;
    int local = t >> 2;
    bool live = (w < NN);
    float dis = 0.f;

    if (live) {
        float4 a = gather_chunk(d_g, w, q);
        dis = d_dis[w];
        sH[local][q * 4 + 0] = fmaxf(fmaf(dis, a.x, sb[q * 4 + 0]), 0.f);
        sH[local][q * 4 + 1] = fmaxf(fmaf(dis, a.y, sb[q * 4 + 1]), 0.f);
        sH[local][q * 4 + 2] = fmaxf(fmaf(dis, a.z, sb[q * 4 + 2]), 0.f);
        sH[local][q * 4 + 3] = fmaxf(fmaf(dis, a.w, sb[q * 4 + 3]), 0.f);
    }
    __syncthreads();
    if (!live) return;

    float h1[F];
#pragma unroll
    for (int k = 0; k < F; k++) h1[k] = sH[local][k];

    float4 h2;
    float* hp = &h2.x;
#pragma unroll
    for (int jj = 0; jj < 4; jj++) {
        int col = q * 4 + jj;
        float s = 0.f;
#pragma unroll
        for (int k = 0; k < F; k++) s = fmaf(h1[k], sW[k * F + col], s);
        hp[jj] = s * dis;
    }
    ((float4*)d_g2)[w * 4 + q] = h2;
}

// Gather pass 2 (reads d_g2) fused with layer-2 finalize + FC head:
// partial = relu(dis*acc + b2).wfc (per chunk) -> smem 4-way reduce -> out
__global__ void k_gather2(const float* __restrict__ b2, const float* __restrict__ Wfc,
                          const float* __restrict__ bfc, float* __restrict__ out) {
    __shared__ float sb[F];
    __shared__ float sw[F];
    __shared__ float sP[64][5];         // padded partials
    __shared__ float sbias;
    int t = threadIdx.x;
    if (t < F) { sb[t] = b2[t]; sw[t] = Wfc[t]; }
    if (t == 0) sbias = bfc[0];
    __syncthreads();

    int tid = blockIdx.x * blockDim.x + t;
    int w = tid >> 2;
    int q = tid & 3;
    int local = t >> 2;
    bool live = (w < NN);

    if (live) {
        float4 a = gather_chunk(d_g2, w, q);
        float dis = d_dis[w];
        int k0 = q * 4;
        float p;
        p  = fmaxf(fmaf(dis, a.x, sb[k0 + 0]), 0.f) * sw[k0 + 0];
        p += fmaxf(fmaf(dis, a.y, sb[k0 + 1]), 0.f) * sw[k0 + 1];
        p += fmaxf(fmaf(dis, a.z, sb[k0 + 2]), 0.f) * sw[k0 + 2];
        p += fmaxf(fmaf(dis, a.w, sb[k0 + 3]), 0.f) * sw[k0 + 3];
        sP[local][q] = p;
    }
    __syncthreads();
    if (live && q == 0)
        out[w] = (sP[local][0] + sP[local][1]) + (sP[local][2] + sP[local][3]) + sbias;
}

extern "C" void kernel_launch(void* const* d_in, const int* in_sizes, int n_in,
                              void* d_out, int out_size) {
    const float* x   = (const float*)d_in[0];
    const int*   ei  = (const int*)d_in[1];     // int32 (JAX x64 disabled)
    const float* W1  = (const float*)d_in[2];
    const float* b1  = (const float*)d_in[3];
    const float* W2  = (const float*)d_in[4];
    const float* b2  = (const float*)d_in[5];
    const float* Wfc = (const float*)d_in[6];
    const float* bfc = (const float*)d_in[7];
    float* out = (float*)d_out;

    const int TB = 256;
    const int nodeBlocks   = NBLK;
    const int edge8Blocks  = (NE / 8 + TB - 1) / TB;
    const int gatherBlocks = (NN * 4 + TB - 1) / TB;

    k_zero<<<nodeBlocks, TB>>>();
    k_build<<<edge8Blocks, TB>>>(ei);
    k_l1_init<<<nodeBlocks, TB>>>(x, W1);
    k_gather1<<<gatherBlocks, TB>>>(b1, W2);
    k_gather2<<<gatherBlocks, TB>>>(b2, Wfc, bfc, out);
}